// round 15
// baseline (speedup 1.0000x reference)
#include <cuda_runtime.h>

#define NN 50000
#define EE 800000
#define TT 12
#define HIDD 128
#define NF 35
#define NCOLS 13   // T+1
#define NSLOT 13   // 12 env + 1 coords, float4 each
#define NCHUNK 49  // ceil(NN/1024)

typedef unsigned long long ull;

struct __align__(8) EW { int v; float w; };

// ---------------- device scratch (static, no allocations) ----------------
__device__ float4 g_feat[NN*NSLOT];
__device__ float4 g_P1o [NN*NSLOT];
__device__ float4 g_P1i [NN*NSLOT];
__device__ float4 g_P2o [NN*NSLOT];
__device__ float4 g_P2i [NN*NSLOT];
__device__ float  g_s  [NN];
__device__ float  g_so [NN], g_si [NN];
__device__ float  g_so2[NN], g_si2[NN];
__device__ float  g_deg_out[NN], g_deg_in[NN];
__device__ float  g_inv_out[NN], g_inv_in[NN];
__device__ int    g_cnt_out[NN], g_cnt_in[NN];
__device__ int    g_off_out[NN+1], g_off_in[NN+1];
__device__ int    g_fill_out[NN], g_fill_in[NN];
__device__ EW     g_ew_out[EE], g_ew_in[EE];
__device__ __align__(16) float2 g_W2[NF*HIDD];
__device__ __align__(16) float2 g_b2[HIDD];
__device__ float  g_linW[HIDD];
__device__ float  g_linb;

// ---------------- tiny asm helpers ---------------------------------------
__device__ __forceinline__ void ffma2(ull& d, ull a, ull b)
{
    asm("fma.rn.f32x2 %0, %1, %2, %0;" : "+l"(d) : "l"(a), "l"(b));
}
__device__ __forceinline__ ull packf2(float x, float y)
{
    ull r; asm("mov.b64 %0, {%1, %2};" : "=l"(r) : "f"(x), "f"(y)); return r;
}
__device__ __forceinline__ void unpackf2(float& x, float& y, ull v)
{
    asm("mov.b64 {%0, %1}, %2;" : "=f"(x), "=f"(y) : "l"(v));
}
__device__ __forceinline__ float tanh_hw(float x)
{
    float r; asm("tanh.approx.f32 %0, %1;" : "=f"(r) : "f"(x)); return r;
}

// ---------------- fused setup: node init + degree atomics -----------------
#define NB_INIT ((NN + 255)/256)
#define NB_DEG  (EE/256)

__global__ void k_setupA(const float* __restrict__ x,
                         const float* __restrict__ env,
                         const float* __restrict__ coords,
                         const int*   __restrict__ ei,
                         const float* __restrict__ ew,
                         float* __restrict__ pred)
{
    if (blockIdx.x < NB_INIT) {
        int n = blockIdx.x * 256 + threadIdx.x;
        if (n >= NN) return;
        float x0 = x[n * TT + 0];
        pred[n * NCOLS + 0] = x0;
        g_s[n] = x0;
        #pragma unroll
        for (int t = 0; t < TT; ++t) {
            float4 e;
            e.x = env[n*48 + 0*12 + t];
            e.y = env[n*48 + 1*12 + t];
            e.z = env[n*48 + 2*12 + t];
            e.w = env[n*48 + 3*12 + t];
            g_feat[n*NSLOT + t] = e;
        }
        g_feat[n*NSLOT + 12] = make_float4(coords[2*n], coords[2*n+1], 0.f, 0.f);
    } else {
        int e = (blockIdx.x - NB_INIT) * 256 + threadIdx.x;
        if (e >= EE) return;
        int r = ei[e];
        int c = ei[EE + e];
        float w = ew[e];
        atomicAdd(&g_deg_out[r], w);
        atomicAdd(&g_deg_in [c], w);
        atomicAdd(&g_cnt_out[r], 1);
        atomicAdd(&g_cnt_in [c], 1);
    }
}

// ---------------- single-pass scan: self-computed carry -------------------
__global__ void __launch_bounds__(1024) k_scan1p()
{
    __shared__ int wsum[32];
    __shared__ int csum[32];
    int b = blockIdx.x;
    int dir = (b >= NCHUNK);
    int chunk = dir ? b - NCHUNK : b;
    const int* cnt = dir ? g_cnt_in  : g_cnt_out;
    int*   off = dir ? g_off_in  : g_off_out;
    const float* deg = dir ? g_deg_in : g_deg_out;
    float* inv = dir ? g_inv_in  : g_inv_out;
    int*   fil = dir ? g_fill_in : g_fill_out;

    int t = threadIdx.x;
    int lane = t & 31, wid = t >> 5;

    int part = 0;
    for (int i = t; i < chunk*1024; i += 1024) part += cnt[i];
    #pragma unroll
    for (int o = 16; o > 0; o >>= 1) part += __shfl_xor_sync(0xffffffffu, part, o);
    if (lane == 0) csum[wid] = part;
    __syncthreads();
    if (wid == 0) {
        int v = csum[lane];
        #pragma unroll
        for (int o = 16; o > 0; o >>= 1) v += __shfl_xor_sync(0xffffffffu, v, o);
        if (lane == 0) csum[0] = v;
    }
    __syncthreads();
    int carry = csum[0];

    int n = chunk*1024 + t;
    int v = (n < NN) ? cnt[n] : 0;
    int s = v;
    #pragma unroll
    for (int o = 1; o < 32; o <<= 1) {
        int u = __shfl_up_sync(0xffffffffu, s, o);
        if (lane >= o) s += u;
    }
    if (lane == 31) wsum[wid] = s;
    __syncthreads();
    if (wid == 0) {
        int ws = wsum[lane];
        #pragma unroll
        for (int o = 1; o < 32; o <<= 1) {
            int u = __shfl_up_sync(0xffffffffu, ws, o);
            if (lane >= o) ws += u;
        }
        wsum[lane] = ws;
    }
    __syncthreads();
    int incl = s + ((wid > 0) ? wsum[wid - 1] : 0);
    if (n < NN) {
        off[n] = carry + incl - v;
        float d = deg[n];
        inv[n] = (d > 0.f) ? (1.f / d) : 0.f;
        fil[n] = 0;
    }
    if (chunk == NCHUNK-1 && t == 1023) off[NN] = carry + incl;
}

// ---------------- fused: fill CSR + pack weights + zero cnt/deg -----------
#define NB_FILL (EE/256)
#define NB_WPK  ((NF*HIDD + 2*HIDD + 1 + 255)/256)
#define NB_Z    ((NN + 255)/256)

__global__ void k_fillwpack(const int* __restrict__ ei, const float* __restrict__ ew,
                            const float* __restrict__ Wz, const float* __restrict__ bz,
                            const float* __restrict__ Wh, const float* __restrict__ bh,
                            const float* __restrict__ linW, const float* __restrict__ linb)
{
    if (blockIdx.x < NB_FILL) {
        int e = blockIdx.x * 256 + threadIdx.x;
        if (e >= EE) return;
        int r = ei[e];
        int c = ei[EE + e];
        float w = ew[e];
        int p = g_off_out[r] + atomicAdd(&g_fill_out[r], 1);
        EW q1; q1.v = c; q1.w = w;
        g_ew_out[p] = q1;
        int p2 = g_off_in[c] + atomicAdd(&g_fill_in[c], 1);
        EW q2; q2.v = r; q2.w = w;
        g_ew_in[p2] = q2;
    } else if (blockIdx.x < NB_FILL + NB_WPK) {
        int t = (blockIdx.x - NB_FILL) * 256 + threadIdx.x;
        const int total = NF * HIDD;
        if (t < total) {
            int i = t / HIDD;
            int d = t % HIDD;
            int a, k, c;
            if (i < 7)       { a = 0; k = 0; c = i;      }
            else if (i < 14) { a = 0; k = 1; c = i - 7;  }
            else if (i < 21) { a = 1; k = 1; c = i - 14; }
            else if (i < 28) { a = 0; k = 2; c = i - 21; }
            else             { a = 1; k = 2; c = i - 28; }
            float vz, vh;
            if (i < 7) {
                vz = Wz[((0*3+0)*135 + c)*HIDD + d] + Wz[((1*3+0)*135 + c)*HIDD + d];
                vh = Wh[((0*3+0)*135 + c)*HIDD + d] + Wh[((1*3+0)*135 + c)*HIDD + d];
            } else {
                vz = Wz[((a*3+k)*135 + c)*HIDD + d];
                vh = Wh[((a*3+k)*135 + c)*HIDD + d];
            }
            g_W2[t] = make_float2(vz, vh);
        } else if (t < total + HIDD) {
            int d = t - total;
            g_b2[d] = make_float2(bz[d], bh[d]);
        } else if (t < total + 2*HIDD) {
            int d = t - total - HIDD;
            g_linW[d] = linW[d];
        } else if (t == total + 2*HIDD) {
            g_linb = linb[0];
        }
    } else {
        int n = (blockIdx.x - NB_FILL - NB_WPK) * 256 + threadIdx.x;
        if (n < NN) {
            g_cnt_out[n] = 0; g_cnt_in[n] = 0;
            g_deg_out[n] = 0.f; g_deg_in[n] = 0.f;
        }
    }
}

// ---------------- static props: 32 lanes/node-dir, 2 edges in flight ------
// half-warp h processes edges beg+h, beg+h+2, ... ; lane%16 = feature slot.
__global__ void __launch_bounds__(256) k_sprop1()
{
    int gt = blockIdx.x * 256 + threadIdx.x;
    int k = gt & 15;
    int h = (gt >> 4) & 1;          // half-warp: edge parity
    int slot = gt >> 5;             // [0, 2*NN)
    if (slot >= 2*NN) return;
    int dir = (slot >= NN);
    int r = dir ? slot - NN : slot;
    const int* off = dir ? g_off_in : g_off_out;
    const EW*  ew  = dir ? g_ew_in  : g_ew_out;
    float inv      = dir ? g_inv_in[r] : g_inv_out[r];
    int beg = off[r], end = off[r+1];
    int kk = (k < NSLOT) ? k : NSLOT - 1;

    float4 acc = make_float4(0.f, 0.f, 0.f, 0.f);
    #pragma unroll 2
    for (int e = beg + h; e < end; e += 2) {
        EW q = ew[e];
        float4 f = g_feat[q.v * NSLOT + kk];
        acc.x = fmaf(q.w, f.x, acc.x);
        acc.y = fmaf(q.w, f.y, acc.y);
        acc.z = fmaf(q.w, f.z, acc.z);
        acc.w = fmaf(q.w, f.w, acc.w);
    }
    // combine the two half-warps (lane k <-> lane k+16)
    acc.x += __shfl_xor_sync(0xffffffffu, acc.x, 16);
    acc.y += __shfl_xor_sync(0xffffffffu, acc.y, 16);
    acc.z += __shfl_xor_sync(0xffffffffu, acc.z, 16);
    acc.w += __shfl_xor_sync(0xffffffffu, acc.w, 16);
    if (h == 0 && k < NSLOT) {
        float4* dst = dir ? g_P1i : g_P1o;
        dst[r*NSLOT + k] = make_float4(inv*acc.x, inv*acc.y, inv*acc.z, inv*acc.w);
    }
}

__global__ void __launch_bounds__(256) k_sprop2()
{
    int gt = blockIdx.x * 256 + threadIdx.x;
    int k = gt & 15;
    int h = (gt >> 4) & 1;
    int slot = gt >> 5;
    if (slot >= 2*NN) return;
    int dir = (slot >= NN);
    int r = dir ? slot - NN : slot;
    const int* off = dir ? g_off_in : g_off_out;
    const EW*  ew  = dir ? g_ew_in  : g_ew_out;
    float inv      = dir ? g_inv_in[r] : g_inv_out[r];
    const float4* src = dir ? g_P1i : g_P1o;
    int beg = off[r], end = off[r+1];
    int kk = (k < NSLOT) ? k : NSLOT - 1;

    float4 acc = make_float4(0.f, 0.f, 0.f, 0.f);
    #pragma unroll 2
    for (int e = beg + h; e < end; e += 2) {
        EW q = ew[e];
        float4 f = src[q.v * NSLOT + kk];
        acc.x = fmaf(q.w, f.x, acc.x);
        acc.y = fmaf(q.w, f.y, acc.y);
        acc.z = fmaf(q.w, f.z, acc.z);
        acc.w = fmaf(q.w, f.w, acc.w);
    }
    acc.x += __shfl_xor_sync(0xffffffffu, acc.x, 16);
    acc.y += __shfl_xor_sync(0xffffffffu, acc.y, 16);
    acc.z += __shfl_xor_sync(0xffffffffu, acc.z, 16);
    acc.w += __shfl_xor_sync(0xffffffffu, acc.w, 16);
    if (h == 0 && k < NSLOT) {
        float s2 = 2.f * inv;
        float4 x0 = g_feat[r*NSLOT + k];
        float4* dst = dir ? g_P2i : g_P2o;
        dst[r*NSLOT + k] = make_float4(s2*acc.x - x0.x, s2*acc.y - x0.y,
                                       s2*acc.z - x0.z, s2*acc.w - x0.w);
    }
}

// ---------------- dynamic scalar first-order props (4 lanes, MLP2) --------
__global__ void k_dprop1()
{
    int tid = blockIdx.x * blockDim.x + threadIdx.x;   // 2*NN*4 threads
    int lane = tid & 3;
    int idx = tid >> 2;
    if (idx >= 2*NN) return;
    int dir = (idx >= NN);
    int r = dir ? idx - NN : idx;
    const int* off = dir ? g_off_in : g_off_out;
    const EW*  ew  = dir ? g_ew_in  : g_ew_out;
    int beg = off[r], end = off[r+1];
    float a0 = 0.f, a1 = 0.f;
    int e = beg + lane;
    for (; e + 4 < end; e += 8) {
        EW q0 = ew[e];
        EW q1 = ew[e + 4];
        a0 = fmaf(q0.w, g_s[q0.v], a0);
        a1 = fmaf(q1.w, g_s[q1.v], a1);
    }
    for (; e < end; e += 4) {
        EW q = ew[e];
        a0 = fmaf(q.w, g_s[q.v], a0);
    }
    float acc = a0 + a1;
    acc += __shfl_xor_sync(0xffffffffu, acc, 1);
    acc += __shfl_xor_sync(0xffffffffu, acc, 2);
    if (lane == 0) {
        float inv = dir ? g_inv_in[r] : g_inv_out[r];
        (dir ? g_si : g_so)[r] = inv * acc;
    }
}

// ---------------- dynamic scalar second-order props (4 lanes, MLP2) -------
__global__ void k_dprop2()
{
    int tid = blockIdx.x * blockDim.x + threadIdx.x;   // 2*NN*4 threads
    int lane = tid & 3;
    int idx = tid >> 2;
    if (idx >= 2*NN) return;
    int dir = (idx >= NN);
    int r = dir ? idx - NN : idx;
    const int* off = dir ? g_off_in : g_off_out;
    const EW*  ew  = dir ? g_ew_in  : g_ew_out;
    const float* src = dir ? g_si : g_so;
    int beg = off[r], end = off[r+1];
    float a0 = 0.f, a1 = 0.f;
    int e = beg + lane;
    for (; e + 4 < end; e += 8) {
        EW q0 = ew[e];
        EW q1 = ew[e + 4];
        a0 = fmaf(q0.w, src[q0.v], a0);
        a1 = fmaf(q1.w, src[q1.v], a1);
    }
    for (; e < end; e += 4) {
        EW q = ew[e];
        a0 = fmaf(q.w, src[q.v], a0);
    }
    float acc = a0 + a1;
    acc += __shfl_xor_sync(0xffffffffu, acc, 1);
    acc += __shfl_xor_sync(0xffffffffu, acc, 2);
    if (lane == 0) {
        float inv = dir ? g_inv_in[r] : g_inv_out[r];
        (dir ? g_si2 : g_so2)[r] = 2.f * inv * acc - g_s[r];
    }
}

// ---------------- GEMV: 4 nodes/thread, smem weights, HW tanh -------------
__device__ __forceinline__ float postf(float z, float h, float lw)
{
    // (1-sigmoid(z))*tanh(h) = 0.5*(1 - tanh(z/2)) * tanh(h)
    float tz = tanh_hw(0.5f * z);
    float th = tanh_hw(h);
    float val = 0.5f * (1.f - tz) * th;
    return fmaxf(val, 0.f) * lw;
}

#define NPB 128
#define FSTR 37
#define GEMV_SMEM (NF*HIDD*8 + HIDD*8 + HIDD*4 + NPB*FSTR*4)

__global__ void __launch_bounds__(128) k_gemv(const float* __restrict__ night,
                                              float* __restrict__ pred,
                                              int t)
{
    extern __shared__ __align__(16) char smraw[];
    ull*    shW  = (ull*)smraw;                 // NF*HIDD packed (wz,wh)
    float2* shB2 = (float2*)(shW + NF*HIDD);
    float*  shL  = (float*)(shB2 + HIDD);
    float*  shF  = shL + HIDD;                  // NPB*FSTR

    for (int i = threadIdx.x; i < NF*HIDD; i += 128) shW[i] = ((const ull*)g_W2)[i];
    for (int i = threadIdx.x; i < HIDD; i += 128) { shB2[i] = g_b2[i]; shL[i] = g_linW[i]; }

    int nb = blockIdx.x * NPB;
    // -------- phase A: stage features, 1 thread per node ------------------
    {
        int n = nb + threadIdx.x;
        float* F = shF + threadIdx.x * FSTR;
        if (n < NN) {
            F[0] = g_s[n];
            float4 e = g_feat[n*NSLOT + t];   F[1]=e.x; F[2]=e.y; F[3]=e.z; F[4]=e.w;
            float4 c = g_feat[n*NSLOT + 12];  F[5]=c.x; F[6]=c.y;
            F[7] = g_so[n];
            float4 eo = g_P1o[n*NSLOT + t];   F[8]=eo.x; F[9]=eo.y; F[10]=eo.z; F[11]=eo.w;
            float4 co = g_P1o[n*NSLOT + 12];  F[12]=co.x; F[13]=co.y;
            F[14] = g_si[n];
            float4 ei = g_P1i[n*NSLOT + t];   F[15]=ei.x; F[16]=ei.y; F[17]=ei.z; F[18]=ei.w;
            float4 ci = g_P1i[n*NSLOT + 12];  F[19]=ci.x; F[20]=ci.y;
            F[21] = g_so2[n];
            float4 eo2 = g_P2o[n*NSLOT + t];  F[22]=eo2.x; F[23]=eo2.y; F[24]=eo2.z; F[25]=eo2.w;
            float4 co2 = g_P2o[n*NSLOT + 12]; F[26]=co2.x; F[27]=co2.y;
            F[28] = g_si2[n];
            float4 ei2 = g_P2i[n*NSLOT + t];  F[29]=ei2.x; F[30]=ei2.y; F[31]=ei2.z; F[32]=ei2.w;
            float4 ci2 = g_P2i[n*NSLOT + 12]; F[33]=ci2.x; F[34]=ci2.y;
        } else {
            #pragma unroll
            for (int i2 = 0; i2 < 35; ++i2) F[i2] = 0.f;
        }
    }
    __syncthreads();

    // -------- phase B: quad-node GEMV (each LDS.128 feeds 4 nodes) --------
    int p = threadIdx.x >> 2;     // 0..31 (node quad)
    int q = threadIdx.x & 3;      // d-quarter, lanes 16B apart
    int n0 = nb + p*4;
    const float* F0 = shF + (p*4)     * FSTR;
    const float* F1 = shF + (p*4 + 1) * FSTR;
    const float* F2 = shF + (p*4 + 2) * FSTR;
    const float* F3 = shF + (p*4 + 3) * FSTR;

    float out0 = 0.f, out1 = 0.f, out2 = 0.f, out3 = 0.f;

    #pragma unroll
    for (int dh = 0; dh < 4; ++dh) {
        int dbase = dh*32 + q*2;
        ull acc0[8], acc1[8], acc2[8], acc3[8];
        #pragma unroll
        for (int j = 0; j < 4; ++j) {
            int d = dbase + j*8;
            ull b0 = ((const ull*)shB2)[d];
            ull b1 = ((const ull*)shB2)[d+1];
            acc0[2*j] = b0; acc0[2*j+1] = b1;
            acc1[2*j] = b0; acc1[2*j+1] = b1;
            acc2[2*j] = b0; acc2[2*j+1] = b1;
            acc3[2*j] = b0; acc3[2*j+1] = b1;
        }
        const ull* wbase = shW + dbase;
        #pragma unroll 5
        for (int i = 0; i < NF; ++i) {
            ull f0p = packf2(F0[i], F0[i]);
            ull f1p = packf2(F1[i], F1[i]);
            ull f2p = packf2(F2[i], F2[i]);
            ull f3p = packf2(F3[i], F3[i]);
            const ull* w = wbase + i*HIDD;
            #pragma unroll
            for (int j = 0; j < 4; ++j) {
                ulonglong2 wv = *(const ulonglong2*)(w + j*8);
                ffma2(acc0[2*j],   wv.x, f0p);
                ffma2(acc0[2*j+1], wv.y, f0p);
                ffma2(acc1[2*j],   wv.x, f1p);
                ffma2(acc1[2*j+1], wv.y, f1p);
                ffma2(acc2[2*j],   wv.x, f2p);
                ffma2(acc2[2*j+1], wv.y, f2p);
                ffma2(acc3[2*j],   wv.x, f3p);
                ffma2(acc3[2*j+1], wv.y, f3p);
            }
        }
        #pragma unroll
        for (int j = 0; j < 4; ++j) {
            int d = dbase + j*8;
            float lw0 = shL[d], lw1 = shL[d+1];
            float z, h;
            unpackf2(z, h, acc0[2*j]);   out0 += postf(z, h, lw0);
            unpackf2(z, h, acc0[2*j+1]); out0 += postf(z, h, lw1);
            unpackf2(z, h, acc1[2*j]);   out1 += postf(z, h, lw0);
            unpackf2(z, h, acc1[2*j+1]); out1 += postf(z, h, lw1);
            unpackf2(z, h, acc2[2*j]);   out2 += postf(z, h, lw0);
            unpackf2(z, h, acc2[2*j+1]); out2 += postf(z, h, lw1);
            unpackf2(z, h, acc3[2*j]);   out3 += postf(z, h, lw0);
            unpackf2(z, h, acc3[2*j+1]); out3 += postf(z, h, lw1);
        }
    }

    out0 += __shfl_xor_sync(0xffffffffu, out0, 1);
    out0 += __shfl_xor_sync(0xffffffffu, out0, 2);
    out1 += __shfl_xor_sync(0xffffffffu, out1, 1);
    out1 += __shfl_xor_sync(0xffffffffu, out1, 2);
    out2 += __shfl_xor_sync(0xffffffffu, out2, 1);
    out2 += __shfl_xor_sync(0xffffffffu, out2, 2);
    out3 += __shfl_xor_sync(0xffffffffu, out3, 1);
    out3 += __shfl_xor_sync(0xffffffffu, out3, 2);

    if (q == 0) {
        float lb = g_linb;
        #pragma unroll
        for (int k = 0; k < 4; ++k) {
            int n = n0 + k;
            if (n < NN) {
                float ov = (k == 0 ? out0 : k == 1 ? out1 : k == 2 ? out2 : out3);
                float o = (ov + lb) * night[n*NCOLS + (t+1)];
                pred[n*NCOLS + (t+1)] = o;
                g_s[n] = o;
            }
        }
    }
}

// ---------------- host launcher -------------------------------------------
extern "C" void kernel_launch(void* const* d_in, const int* in_sizes, int n_in,
                              void* d_out, int out_size)
{
    const float *x, *env, *coords, *ew, *night, *Wz, *bz, *Wh, *bh, *linW, *linb;
    const int *eidx;

    if (in_sizes[3] == 2*EE) {
        x      = (const float*)d_in[0];
        env    = (const float*)d_in[1];
        coords = (const float*)d_in[2];
        eidx   = (const int*)  d_in[3];
        ew     = (const float*)d_in[4];
        night  = (const float*)d_in[5];
        Wz     = (const float*)d_in[6];
        bz     = (const float*)d_in[7];
        Wh     = (const float*)d_in[10];
        bh     = (const float*)d_in[11];
        linW   = (const float*)d_in[12];
        linb   = (const float*)d_in[13];
    } else {
        x      = (const float*)d_in[0];
        env    = (const float*)d_in[1];
        coords = (const float*)d_in[2];
        ew     = (const float*)d_in[3];
        night  = (const float*)d_in[4];
        Wz     = (const float*)d_in[5];
        bz     = (const float*)d_in[6];
        Wh     = (const float*)d_in[9];
        bh     = (const float*)d_in[10];
        linW   = (const float*)d_in[11];
        linb   = (const float*)d_in[12];
        eidx   = (const int*)  d_in[13];
    }

    float* pred = (float*)d_out;

    cudaFuncSetAttribute(k_gemv, cudaFuncAttributeMaxDynamicSharedMemorySize, GEMV_SMEM);

    k_setupA<<<NB_INIT + NB_DEG, 256>>>(x, env, coords, eidx, ew, pred);
    k_scan1p<<<2*NCHUNK, 1024>>>();
    k_fillwpack<<<NB_FILL + NB_WPK + NB_Z, 256>>>(eidx, ew, Wz, bz, Wh, bh, linW, linb);
    int sgrid = (2*NN*32 + 255)/256;
    k_sprop1<<<sgrid, 256>>>();
    k_sprop2<<<sgrid, 256>>>();

    int dgrid = (2*NN*4 + 127)/128;
    int ggrid = (NN + NPB - 1)/NPB;
    for (int t = 0; t < TT; ++t) {
        k_dprop1<<<dgrid, 128>>>();
        k_dprop2<<<dgrid, 128>>>();
        k_gemv  <<<ggrid, 128, GEMV_SMEM>>>(night, pred, t);
    }
}

// round 16
// speedup vs baseline: 1.0395x; 1.0395x over previous
#include <cuda_runtime.h>

#define NN 50000
#define EE 800000
#define TT 12
#define HIDD 128
#define NF 35
#define NCOLS 13   // T+1
#define NSLOT 13   // 12 env + 1 coords, float4 each
#define NCHUNK 49  // ceil(NN/1024)

typedef unsigned long long ull;

struct __align__(8) EW { int v; float w; };

// ---------------- device scratch (static, no allocations) ----------------
__device__ float4 g_feat [NN*NSLOT];   // [n][slot] (sprop gathers, sprop2 x0)
__device__ float4 g_featT[NSLOT*NN];   // [slot][n] (gemv coalesced)
__device__ float4 g_P1o  [NN*NSLOT];   // [n][slot] (sprop2 gather)
__device__ float4 g_P1i  [NN*NSLOT];
__device__ float4 g_P1oT [NSLOT*NN];   // [slot][n] (gemv)
__device__ float4 g_P1iT [NSLOT*NN];
__device__ float4 g_P2oT [NSLOT*NN];   // [slot][n] (gemv)
__device__ float4 g_P2iT [NSLOT*NN];
__device__ float  g_s  [NN];
__device__ float  g_so [NN], g_si [NN];
__device__ float  g_so2[NN], g_si2[NN];
__device__ float  g_deg_out[NN], g_deg_in[NN];
__device__ float  g_inv_out[NN], g_inv_in[NN];
__device__ int    g_cnt_out[NN], g_cnt_in[NN];
__device__ int    g_off_out[NN+1], g_off_in[NN+1];
__device__ int    g_fill_out[NN], g_fill_in[NN];
__device__ EW     g_ew_out[EE], g_ew_in[EE];
__device__ __align__(16) float2 g_W2[NF*HIDD];
__device__ __align__(16) float2 g_b2[HIDD];
__device__ float  g_linW[HIDD];
__device__ float  g_linb;

// ---------------- tiny asm helpers ---------------------------------------
__device__ __forceinline__ void ffma2(ull& d, ull a, ull b)
{
    asm("fma.rn.f32x2 %0, %1, %2, %0;" : "+l"(d) : "l"(a), "l"(b));
}
__device__ __forceinline__ ull packf2(float x, float y)
{
    ull r; asm("mov.b64 %0, {%1, %2};" : "=l"(r) : "f"(x), "f"(y)); return r;
}
__device__ __forceinline__ void unpackf2(float& x, float& y, ull v)
{
    asm("mov.b64 {%0, %1}, %2;" : "=f"(x), "=f"(y) : "l"(v));
}
__device__ __forceinline__ float tanh_hw(float x)
{
    float r; asm("tanh.approx.f32 %0, %1;" : "=f"(r) : "f"(x)); return r;
}

// ---------------- fused setup: node init + degree atomics -----------------
#define NB_INIT ((NN + 255)/256)
#define NB_DEG  (EE/256)

__global__ void k_setupA(const float* __restrict__ x,
                         const float* __restrict__ env,
                         const float* __restrict__ coords,
                         const int*   __restrict__ ei,
                         const float* __restrict__ ew,
                         float* __restrict__ pred)
{
    if (blockIdx.x < NB_INIT) {
        int n = blockIdx.x * 256 + threadIdx.x;
        if (n >= NN) return;
        float x0 = x[n * TT + 0];
        pred[n * NCOLS + 0] = x0;
        g_s[n] = x0;
        #pragma unroll
        for (int t = 0; t < TT; ++t) {
            float4 e;
            e.x = env[n*48 + 0*12 + t];
            e.y = env[n*48 + 1*12 + t];
            e.z = env[n*48 + 2*12 + t];
            e.w = env[n*48 + 3*12 + t];
            g_feat [n*NSLOT + t] = e;
            g_featT[t*NN + n]    = e;
        }
        float4 c = make_float4(coords[2*n], coords[2*n+1], 0.f, 0.f);
        g_feat [n*NSLOT + 12] = c;
        g_featT[12*NN + n]    = c;
    } else {
        int e = (blockIdx.x - NB_INIT) * 256 + threadIdx.x;
        if (e >= EE) return;
        int r = ei[e];
        int c = ei[EE + e];
        float w = ew[e];
        atomicAdd(&g_deg_out[r], w);
        atomicAdd(&g_deg_in [c], w);
        atomicAdd(&g_cnt_out[r], 1);
        atomicAdd(&g_cnt_in [c], 1);
    }
}

// ---------------- single-pass scan: self-computed carry -------------------
__global__ void __launch_bounds__(1024) k_scan1p()
{
    __shared__ int wsum[32];
    __shared__ int csum[32];
    int b = blockIdx.x;
    int dir = (b >= NCHUNK);
    int chunk = dir ? b - NCHUNK : b;
    const int* cnt = dir ? g_cnt_in  : g_cnt_out;
    int*   off = dir ? g_off_in  : g_off_out;
    const float* deg = dir ? g_deg_in : g_deg_out;
    float* inv = dir ? g_inv_in  : g_inv_out;
    int*   fil = dir ? g_fill_in : g_fill_out;

    int t = threadIdx.x;
    int lane = t & 31, wid = t >> 5;

    int part = 0;
    for (int i = t; i < chunk*1024; i += 1024) part += cnt[i];
    #pragma unroll
    for (int o = 16; o > 0; o >>= 1) part += __shfl_xor_sync(0xffffffffu, part, o);
    if (lane == 0) csum[wid] = part;
    __syncthreads();
    if (wid == 0) {
        int v = csum[lane];
        #pragma unroll
        for (int o = 16; o > 0; o >>= 1) v += __shfl_xor_sync(0xffffffffu, v, o);
        if (lane == 0) csum[0] = v;
    }
    __syncthreads();
    int carry = csum[0];

    int n = chunk*1024 + t;
    int v = (n < NN) ? cnt[n] : 0;
    int s = v;
    #pragma unroll
    for (int o = 1; o < 32; o <<= 1) {
        int u = __shfl_up_sync(0xffffffffu, s, o);
        if (lane >= o) s += u;
    }
    if (lane == 31) wsum[wid] = s;
    __syncthreads();
    if (wid == 0) {
        int ws = wsum[lane];
        #pragma unroll
        for (int o = 1; o < 32; o <<= 1) {
            int u = __shfl_up_sync(0xffffffffu, ws, o);
            if (lane >= o) ws += u;
        }
        wsum[lane] = ws;
    }
    __syncthreads();
    int incl = s + ((wid > 0) ? wsum[wid - 1] : 0);
    if (n < NN) {
        off[n] = carry + incl - v;
        float d = deg[n];
        inv[n] = (d > 0.f) ? (1.f / d) : 0.f;
        fil[n] = 0;
    }
    if (chunk == NCHUNK-1 && t == 1023) off[NN] = carry + incl;
}

// ---------------- fused: fill CSR + pack weights + zero cnt/deg -----------
#define NB_FILL (EE/256)
#define NB_WPK  ((NF*HIDD + 2*HIDD + 1 + 255)/256)
#define NB_Z    ((NN + 255)/256)

__global__ void k_fillwpack(const int* __restrict__ ei, const float* __restrict__ ew,
                            const float* __restrict__ Wz, const float* __restrict__ bz,
                            const float* __restrict__ Wh, const float* __restrict__ bh,
                            const float* __restrict__ linW, const float* __restrict__ linb)
{
    if (blockIdx.x < NB_FILL) {
        int e = blockIdx.x * 256 + threadIdx.x;
        if (e >= EE) return;
        int r = ei[e];
        int c = ei[EE + e];
        float w = ew[e];
        int p = g_off_out[r] + atomicAdd(&g_fill_out[r], 1);
        EW q1; q1.v = c; q1.w = w;
        g_ew_out[p] = q1;
        int p2 = g_off_in[c] + atomicAdd(&g_fill_in[c], 1);
        EW q2; q2.v = r; q2.w = w;
        g_ew_in[p2] = q2;
    } else if (blockIdx.x < NB_FILL + NB_WPK) {
        int t = (blockIdx.x - NB_FILL) * 256 + threadIdx.x;
        const int total = NF * HIDD;
        if (t < total) {
            int i = t / HIDD;
            int d = t % HIDD;
            int a, k, c;
            if (i < 7)       { a = 0; k = 0; c = i;      }
            else if (i < 14) { a = 0; k = 1; c = i - 7;  }
            else if (i < 21) { a = 1; k = 1; c = i - 14; }
            else if (i < 28) { a = 0; k = 2; c = i - 21; }
            else             { a = 1; k = 2; c = i - 28; }
            float vz, vh;
            if (i < 7) {
                vz = Wz[((0*3+0)*135 + c)*HIDD + d] + Wz[((1*3+0)*135 + c)*HIDD + d];
                vh = Wh[((0*3+0)*135 + c)*HIDD + d] + Wh[((1*3+0)*135 + c)*HIDD + d];
            } else {
                vz = Wz[((a*3+k)*135 + c)*HIDD + d];
                vh = Wh[((a*3+k)*135 + c)*HIDD + d];
            }
            g_W2[t] = make_float2(vz, vh);
        } else if (t < total + HIDD) {
            int d = t - total;
            g_b2[d] = make_float2(bz[d], bh[d]);
        } else if (t < total + 2*HIDD) {
            int d = t - total - HIDD;
            g_linW[d] = linW[d];
        } else if (t == total + 2*HIDD) {
            g_linb = linb[0];
        }
    } else {
        int n = (blockIdx.x - NB_FILL - NB_WPK) * 256 + threadIdx.x;
        if (n < NN) {
            g_cnt_out[n] = 0; g_cnt_in[n] = 0;
            g_deg_out[n] = 0.f; g_deg_in[n] = 0.f;
        }
    }
}

// ---------------- static props: 16 lanes per node, lane = feature slot ----
__global__ void __launch_bounds__(256) k_sprop1()
{
    int gt = blockIdx.x * 256 + threadIdx.x;
    int k = gt & 15;
    int slot = gt >> 4;
    if (slot >= 2*NN) return;
    int dir = (slot >= NN);
    int r = dir ? slot - NN : slot;
    const int* off = dir ? g_off_in : g_off_out;
    const EW*  ew  = dir ? g_ew_in  : g_ew_out;
    float inv      = dir ? g_inv_in[r] : g_inv_out[r];
    int beg = off[r], end = off[r+1];
    int kk = (k < NSLOT) ? k : NSLOT - 1;

    float4 acc = make_float4(0.f, 0.f, 0.f, 0.f);
    #pragma unroll 4
    for (int e = beg; e < end; ++e) {
        EW q = ew[e];
        float4 f = g_feat[q.v * NSLOT + kk];
        acc.x = fmaf(q.w, f.x, acc.x);
        acc.y = fmaf(q.w, f.y, acc.y);
        acc.z = fmaf(q.w, f.z, acc.z);
        acc.w = fmaf(q.w, f.w, acc.w);
    }
    if (k < NSLOT) {
        float4 res = make_float4(inv*acc.x, inv*acc.y, inv*acc.z, inv*acc.w);
        if (!dir) { g_P1o[r*NSLOT + k] = res; g_P1oT[k*NN + r] = res; }
        else      { g_P1i[r*NSLOT + k] = res; g_P1iT[k*NN + r] = res; }
    }
}

__global__ void __launch_bounds__(256) k_sprop2()
{
    int gt = blockIdx.x * 256 + threadIdx.x;
    int k = gt & 15;
    int slot = gt >> 4;
    if (slot >= 2*NN) return;
    int dir = (slot >= NN);
    int r = dir ? slot - NN : slot;
    const int* off = dir ? g_off_in : g_off_out;
    const EW*  ew  = dir ? g_ew_in  : g_ew_out;
    float inv      = dir ? g_inv_in[r] : g_inv_out[r];
    const float4* src = dir ? g_P1i : g_P1o;
    int beg = off[r], end = off[r+1];
    int kk = (k < NSLOT) ? k : NSLOT - 1;

    float4 acc = make_float4(0.f, 0.f, 0.f, 0.f);
    #pragma unroll 4
    for (int e = beg; e < end; ++e) {
        EW q = ew[e];
        float4 f = src[q.v * NSLOT + kk];
        acc.x = fmaf(q.w, f.x, acc.x);
        acc.y = fmaf(q.w, f.y, acc.y);
        acc.z = fmaf(q.w, f.z, acc.z);
        acc.w = fmaf(q.w, f.w, acc.w);
    }
    if (k < NSLOT) {
        float s2 = 2.f * inv;
        float4 x0 = g_feat[r*NSLOT + k];
        float4* dstT = dir ? g_P2iT : g_P2oT;
        dstT[k*NN + r] = make_float4(s2*acc.x - x0.x, s2*acc.y - x0.y,
                                     s2*acc.z - x0.z, s2*acc.w - x0.w);
    }
}

// ---------------- dynamic scalar first-order props (4 lanes, MLP2) --------
__global__ void k_dprop1()
{
    int tid = blockIdx.x * blockDim.x + threadIdx.x;   // 2*NN*4 threads
    int lane = tid & 3;
    int idx = tid >> 2;
    if (idx >= 2*NN) return;
    int dir = (idx >= NN);
    int r = dir ? idx - NN : idx;
    const int* off = dir ? g_off_in : g_off_out;
    const EW*  ew  = dir ? g_ew_in  : g_ew_out;
    int beg = off[r], end = off[r+1];
    float a0 = 0.f, a1 = 0.f;
    int e = beg + lane;
    for (; e + 4 < end; e += 8) {
        EW q0 = ew[e];
        EW q1 = ew[e + 4];
        a0 = fmaf(q0.w, g_s[q0.v], a0);
        a1 = fmaf(q1.w, g_s[q1.v], a1);
    }
    for (; e < end; e += 4) {
        EW q = ew[e];
        a0 = fmaf(q.w, g_s[q.v], a0);
    }
    float acc = a0 + a1;
    acc += __shfl_xor_sync(0xffffffffu, acc, 1);
    acc += __shfl_xor_sync(0xffffffffu, acc, 2);
    if (lane == 0) {
        float inv = dir ? g_inv_in[r] : g_inv_out[r];
        (dir ? g_si : g_so)[r] = inv * acc;
    }
}

// ---------------- dynamic scalar second-order props (4 lanes, MLP2) -------
__global__ void k_dprop2()
{
    int tid = blockIdx.x * blockDim.x + threadIdx.x;   // 2*NN*4 threads
    int lane = tid & 3;
    int idx = tid >> 2;
    if (idx >= 2*NN) return;
    int dir = (idx >= NN);
    int r = dir ? idx - NN : idx;
    const int* off = dir ? g_off_in : g_off_out;
    const EW*  ew  = dir ? g_ew_in  : g_ew_out;
    const float* src = dir ? g_si : g_so;
    int beg = off[r], end = off[r+1];
    float a0 = 0.f, a1 = 0.f;
    int e = beg + lane;
    for (; e + 4 < end; e += 8) {
        EW q0 = ew[e];
        EW q1 = ew[e + 4];
        a0 = fmaf(q0.w, src[q0.v], a0);
        a1 = fmaf(q1.w, src[q1.v], a1);
    }
    for (; e < end; e += 4) {
        EW q = ew[e];
        a0 = fmaf(q.w, src[q.v], a0);
    }
    float acc = a0 + a1;
    acc += __shfl_xor_sync(0xffffffffu, acc, 1);
    acc += __shfl_xor_sync(0xffffffffu, acc, 2);
    if (lane == 0) {
        float inv = dir ? g_inv_in[r] : g_inv_out[r];
        (dir ? g_si2 : g_so2)[r] = 2.f * inv * acc - g_s[r];
    }
}

// ---------------- GEMV: 4 nodes/thread, coalesced staging, HW tanh --------
__device__ __forceinline__ float postf(float z, float h, float lw)
{
    // (1-sigmoid(z))*tanh(h) = 0.5*(1 - tanh(z/2)) * tanh(h)
    float tz = tanh_hw(0.5f * z);
    float th = tanh_hw(h);
    float val = 0.5f * (1.f - tz) * th;
    return fmaxf(val, 0.f) * lw;
}

#define NPB 128
#define FSTR 37
#define GEMV_SMEM (NF*HIDD*8 + HIDD*8 + HIDD*4 + NPB*FSTR*4)

__global__ void __launch_bounds__(128) k_gemv(const float* __restrict__ night,
                                              float* __restrict__ pred,
                                              int t)
{
    extern __shared__ __align__(16) char smraw[];
    ull*    shW  = (ull*)smraw;                 // NF*HIDD packed (wz,wh)
    float2* shB2 = (float2*)(shW + NF*HIDD);
    float*  shL  = (float*)(shB2 + HIDD);
    float*  shF  = shL + HIDD;                  // NPB*FSTR

    for (int i = threadIdx.x; i < NF*HIDD; i += 128) shW[i] = ((const ull*)g_W2)[i];
    for (int i = threadIdx.x; i < HIDD; i += 128) { shB2[i] = g_b2[i]; shL[i] = g_linW[i]; }

    int nb = blockIdx.x * NPB;
    // -------- phase A: coalesced staging from [slot][n] layouts -----------
    {
        int n = nb + threadIdx.x;
        float* F = shF + threadIdx.x * FSTR;
        if (n < NN) {
            F[0] = g_s[n];
            float4 e = g_featT[t*NN + n];   F[1]=e.x; F[2]=e.y; F[3]=e.z; F[4]=e.w;
            float4 c = g_featT[12*NN + n];  F[5]=c.x; F[6]=c.y;
            F[7] = g_so[n];
            float4 eo = g_P1oT[t*NN + n];   F[8]=eo.x; F[9]=eo.y; F[10]=eo.z; F[11]=eo.w;
            float4 co = g_P1oT[12*NN + n];  F[12]=co.x; F[13]=co.y;
            F[14] = g_si[n];
            float4 ei = g_P1iT[t*NN + n];   F[15]=ei.x; F[16]=ei.y; F[17]=ei.z; F[18]=ei.w;
            float4 ci = g_P1iT[12*NN + n];  F[19]=ci.x; F[20]=ci.y;
            F[21] = g_so2[n];
            float4 eo2 = g_P2oT[t*NN + n];  F[22]=eo2.x; F[23]=eo2.y; F[24]=eo2.z; F[25]=eo2.w;
            float4 co2 = g_P2oT[12*NN + n]; F[26]=co2.x; F[27]=co2.y;
            F[28] = g_si2[n];
            float4 ei2 = g_P2iT[t*NN + n];  F[29]=ei2.x; F[30]=ei2.y; F[31]=ei2.z; F[32]=ei2.w;
            float4 ci2 = g_P2iT[12*NN + n]; F[33]=ci2.x; F[34]=ci2.y;
        } else {
            #pragma unroll
            for (int i2 = 0; i2 < 35; ++i2) F[i2] = 0.f;
        }
    }
    __syncthreads();

    // -------- phase B: quad-node GEMV (each LDS.128 feeds 4 nodes) --------
    int p = threadIdx.x >> 2;     // 0..31 (node quad)
    int q = threadIdx.x & 3;      // d-quarter, lanes 16B apart
    int n0 = nb + p*4;
    const float* F0 = shF + (p*4)     * FSTR;
    const float* F1 = shF + (p*4 + 1) * FSTR;
    const float* F2 = shF + (p*4 + 2) * FSTR;
    const float* F3 = shF + (p*4 + 3) * FSTR;

    float out0 = 0.f, out1 = 0.f, out2 = 0.f, out3 = 0.f;

    #pragma unroll
    for (int dh = 0; dh < 4; ++dh) {
        int dbase = dh*32 + q*2;
        ull acc0[8], acc1[8], acc2[8], acc3[8];
        #pragma unroll
        for (int j = 0; j < 4; ++j) {
            int d = dbase + j*8;
            ull b0 = ((const ull*)shB2)[d];
            ull b1 = ((const ull*)shB2)[d+1];
            acc0[2*j] = b0; acc0[2*j+1] = b1;
            acc1[2*j] = b0; acc1[2*j+1] = b1;
            acc2[2*j] = b0; acc2[2*j+1] = b1;
            acc3[2*j] = b0; acc3[2*j+1] = b1;
        }
        const ull* wbase = shW + dbase;
        #pragma unroll 5
        for (int i = 0; i < NF; ++i) {
            ull f0p = packf2(F0[i], F0[i]);
            ull f1p = packf2(F1[i], F1[i]);
            ull f2p = packf2(F2[i], F2[i]);
            ull f3p = packf2(F3[i], F3[i]);
            const ull* w = wbase + i*HIDD;
            #pragma unroll
            for (int j = 0; j < 4; ++j) {
                ulonglong2 wv = *(const ulonglong2*)(w + j*8);
                ffma2(acc0[2*j],   wv.x, f0p);
                ffma2(acc0[2*j+1], wv.y, f0p);
                ffma2(acc1[2*j],   wv.x, f1p);
                ffma2(acc1[2*j+1], wv.y, f1p);
                ffma2(acc2[2*j],   wv.x, f2p);
                ffma2(acc2[2*j+1], wv.y, f2p);
                ffma2(acc3[2*j],   wv.x, f3p);
                ffma2(acc3[2*j+1], wv.y, f3p);
            }
        }
        #pragma unroll
        for (int j = 0; j < 4; ++j) {
            int d = dbase + j*8;
            float lw0 = shL[d], lw1 = shL[d+1];
            float z, h;
            unpackf2(z, h, acc0[2*j]);   out0 += postf(z, h, lw0);
            unpackf2(z, h, acc0[2*j+1]); out0 += postf(z, h, lw1);
            unpackf2(z, h, acc1[2*j]);   out1 += postf(z, h, lw0);
            unpackf2(z, h, acc1[2*j+1]); out1 += postf(z, h, lw1);
            unpackf2(z, h, acc2[2*j]);   out2 += postf(z, h, lw0);
            unpackf2(z, h, acc2[2*j+1]); out2 += postf(z, h, lw1);
            unpackf2(z, h, acc3[2*j]);   out3 += postf(z, h, lw0);
            unpackf2(z, h, acc3[2*j+1]); out3 += postf(z, h, lw1);
        }
    }

    out0 += __shfl_xor_sync(0xffffffffu, out0, 1);
    out0 += __shfl_xor_sync(0xffffffffu, out0, 2);
    out1 += __shfl_xor_sync(0xffffffffu, out1, 1);
    out1 += __shfl_xor_sync(0xffffffffu, out1, 2);
    out2 += __shfl_xor_sync(0xffffffffu, out2, 1);
    out2 += __shfl_xor_sync(0xffffffffu, out2, 2);
    out3 += __shfl_xor_sync(0xffffffffu, out3, 1);
    out3 += __shfl_xor_sync(0xffffffffu, out3, 2);

    if (q == 0) {
        float lb = g_linb;
        #pragma unroll
        for (int k = 0; k < 4; ++k) {
            int n = n0 + k;
            if (n < NN) {
                float ov = (k == 0 ? out0 : k == 1 ? out1 : k == 2 ? out2 : out3);
                float o = (ov + lb) * night[n*NCOLS + (t+1)];
                pred[n*NCOLS + (t+1)] = o;
                g_s[n] = o;
            }
        }
    }
}

// ---------------- host launcher -------------------------------------------
extern "C" void kernel_launch(void* const* d_in, const int* in_sizes, int n_in,
                              void* d_out, int out_size)
{
    const float *x, *env, *coords, *ew, *night, *Wz, *bz, *Wh, *bh, *linW, *linb;
    const int *eidx;

    if (in_sizes[3] == 2*EE) {
        x      = (const float*)d_in[0];
        env    = (const float*)d_in[1];
        coords = (const float*)d_in[2];
        eidx   = (const int*)  d_in[3];
        ew     = (const float*)d_in[4];
        night  = (const float*)d_in[5];
        Wz     = (const float*)d_in[6];
        bz     = (const float*)d_in[7];
        Wh     = (const float*)d_in[10];
        bh     = (const float*)d_in[11];
        linW   = (const float*)d_in[12];
        linb   = (const float*)d_in[13];
    } else {
        x      = (const float*)d_in[0];
        env    = (const float*)d_in[1];
        coords = (const float*)d_in[2];
        ew     = (const float*)d_in[3];
        night  = (const float*)d_in[4];
        Wz     = (const float*)d_in[5];
        bz     = (const float*)d_in[6];
        Wh     = (const float*)d_in[9];
        bh     = (const float*)d_in[10];
        linW   = (const float*)d_in[11];
        linb   = (const float*)d_in[12];
        eidx   = (const int*)  d_in[13];
    }

    float* pred = (float*)d_out;

    cudaFuncSetAttribute(k_gemv, cudaFuncAttributeMaxDynamicSharedMemorySize, GEMV_SMEM);

    k_setupA<<<NB_INIT + NB_DEG, 256>>>(x, env, coords, eidx, ew, pred);
    k_scan1p<<<2*NCHUNK, 1024>>>();
    k_fillwpack<<<NB_FILL + NB_WPK + NB_Z, 256>>>(eidx, ew, Wz, bz, Wh, bh, linW, linb);
    int sgrid = (2*NN*16 + 255)/256;
    k_sprop1<<<sgrid, 256>>>();
    k_sprop2<<<sgrid, 256>>>();

    int dgrid = (2*NN*4 + 127)/128;
    int ggrid = (NN + NPB - 1)/NPB;
    for (int t = 0; t < TT; ++t) {
        k_dprop1<<<dgrid, 128>>>();
        k_dprop2<<<dgrid, 128>>>();
        k_gemv  <<<ggrid, 128, GEMV_SMEM>>>(night, pred, t);
    }
}